// round 1
// baseline (speedup 1.0000x reference)
#include <cuda_runtime.h>
#include <cstdint>

#define BATCH 16
#define TLEN  2048
#define DIM   512
#define FDIM  256
#define QKV3  768
#define MTOT  (BATCH * TLEN)   // 32768

// Scratch (allocation-free rule: __device__ globals)
__device__ float g_qkv[(size_t)MTOT * QKV3];  // [M, 768]: q|k|v
__device__ float g_ctx[(size_t)MTOT * FDIM];  // [M, 256]

// ---------------------------------------------------------------------------
// Generic tiled GEMM: C[M,N] = A[M,K] @ W[K,N] + bias[N] (+ residual[M,N])
// BM=BN=64, BK=16, 256 threads, 4x4 microtile.
// ---------------------------------------------------------------------------
__global__ void __launch_bounds__(256) gemm_bias_kernel(
    const float* __restrict__ A, const float* __restrict__ W,
    const float* __restrict__ bias, float* __restrict__ C,
    const float* __restrict__ residual,
    int M, int N, int K)
{
    __shared__ float As[64][17];   // [m][k], padded
    __shared__ float Bs[16][68];   // [k][n], padded

    const int bm = blockIdx.y * 64;
    const int bn = blockIdx.x * 64;
    const int t  = threadIdx.x;
    const int ty = t >> 4;         // 0..15  -> rows ty*4..ty*4+3
    const int tx = t & 15;         // 0..15  -> cols tx*4..tx*4+3

    float acc[4][4] = {};

    for (int k0 = 0; k0 < K; k0 += 16) {
        // Load A tile 64x16 (one float4 per thread)
        {
            const int r  = t >> 2;
            const int kk = (t & 3) << 2;
            const float4 a4 = *(const float4*)(A + (size_t)(bm + r) * K + k0 + kk);
            As[r][kk + 0] = a4.x; As[r][kk + 1] = a4.y;
            As[r][kk + 2] = a4.z; As[r][kk + 3] = a4.w;
        }
        // Load B tile 16x64 (one float4 per thread)
        {
            const int kk = t >> 4;
            const int n  = (t & 15) << 2;
            const float4 b4 = *(const float4*)(W + (size_t)(k0 + kk) * N + bn + n);
            Bs[kk][n + 0] = b4.x; Bs[kk][n + 1] = b4.y;
            Bs[kk][n + 2] = b4.z; Bs[kk][n + 3] = b4.w;
        }
        __syncthreads();

        #pragma unroll
        for (int kk = 0; kk < 16; kk++) {
            float a0 = As[ty * 4 + 0][kk];
            float a1 = As[ty * 4 + 1][kk];
            float a2 = As[ty * 4 + 2][kk];
            float a3 = As[ty * 4 + 3][kk];
            float4 b4 = *(const float4*)(&Bs[kk][tx * 4]);
            acc[0][0] += a0 * b4.x; acc[0][1] += a0 * b4.y; acc[0][2] += a0 * b4.z; acc[0][3] += a0 * b4.w;
            acc[1][0] += a1 * b4.x; acc[1][1] += a1 * b4.y; acc[1][2] += a1 * b4.z; acc[1][3] += a1 * b4.w;
            acc[2][0] += a2 * b4.x; acc[2][1] += a2 * b4.y; acc[2][2] += a2 * b4.z; acc[2][3] += a2 * b4.w;
            acc[3][0] += a3 * b4.x; acc[3][1] += a3 * b4.y; acc[3][2] += a3 * b4.z; acc[3][3] += a3 * b4.w;
        }
        __syncthreads();
    }

    const float4 bia = *(const float4*)(bias + bn + tx * 4);
    #pragma unroll
    for (int i = 0; i < 4; i++) {
        const size_t row = (size_t)(bm + ty * 4 + i);
        float4 o;
        o.x = acc[i][0] + bia.x;
        o.y = acc[i][1] + bia.y;
        o.z = acc[i][2] + bia.z;
        o.w = acc[i][3] + bia.w;
        if (residual != nullptr) {
            const float4 r4 = *(const float4*)(residual + row * N + bn + tx * 4);
            o.x += r4.x; o.y += r4.y; o.z += r4.z; o.w += r4.w;
        }
        *(float4*)(C + row * N + bn + tx * 4) = o;
    }
}

// ---------------------------------------------------------------------------
// Flash attention (fp32): per CTA: 1 batch, 64 query rows; loop over 64-key
// tiles with online softmax. O accumulator in registers (4 rows x 16 cols).
// smem rows padded to 260 floats (Q/KV) and 65 (S) for bank-conflict freedom.
// ---------------------------------------------------------------------------
#define SQ_STRIDE 260
#define SS_STRIDE 65

__global__ void __launch_bounds__(256) flash_attn_kernel(
    const float* __restrict__ qkv, float* __restrict__ ctx)
{
    extern __shared__ float smem[];
    float* sQ   = smem;                              // 64 x 260
    float* sKV  = sQ + 64 * SQ_STRIDE;               // 64 x 260
    float* sS   = sKV + 64 * SQ_STRIDE;              // 64 x 65
    float* sm   = sS + 64 * SS_STRIDE;               // 64
    float* sl   = sm + 64;                           // 64
    float* sfac = sl + 64;                           // 64

    const int b  = blockIdx.y;
    const int q0 = blockIdx.x * 64;
    const int t  = threadIdx.x;
    const int ty = t >> 4;     // row group: rows ty*4..ty*4+3
    const int tx = t & 15;     // col group: cols tx*16..tx*16+15 (for O)

    // Load Q tile (64 x 256)
    const float* qbase = qkv + ((size_t)b * TLEN + q0) * QKV3;
    for (int idx = t; idx < 64 * 64; idx += 256) {
        const int r = idx >> 6, c4 = (idx & 63) << 2;
        *(float4*)(sQ + r * SQ_STRIDE + c4) = *(const float4*)(qbase + (size_t)r * QKV3 + c4);
    }
    if (t < 64) { sm[t] = -1e30f; sl[t] = 0.0f; }

    float O[4][16] = {};
    const float scale = 0.0625f;  // 1/sqrt(256)

    for (int j0 = 0; j0 < TLEN; j0 += 64) {
        __syncthreads();  // previous PV reads of sKV/sS complete; sQ/sm visible on iter 0

        // Load K tile
        const float* kbase = qkv + ((size_t)b * TLEN + j0) * QKV3 + FDIM;
        for (int idx = t; idx < 64 * 64; idx += 256) {
            const int r = idx >> 6, c4 = (idx & 63) << 2;
            *(float4*)(sKV + r * SQ_STRIDE + c4) = *(const float4*)(kbase + (size_t)r * QKV3 + c4);
        }
        __syncthreads();

        // S(64x64) = Q @ K^T, 4x4 microtile per thread (rows ty*4, cols tx*4)
        {
            float s[4][4] = {};
            const float* qrow0 = sQ + (ty * 4) * SQ_STRIDE;
            const float* krow0 = sKV + (tx * 4) * SQ_STRIDE;
            #pragma unroll 4
            for (int k = 0; k < FDIM; k += 4) {
                float4 a[4], bb[4];
                #pragma unroll
                for (int i = 0; i < 4; i++) a[i]  = *(const float4*)(qrow0 + i * SQ_STRIDE + k);
                #pragma unroll
                for (int j = 0; j < 4; j++) bb[j] = *(const float4*)(krow0 + j * SQ_STRIDE + k);
                #pragma unroll
                for (int i = 0; i < 4; i++)
                    #pragma unroll
                    for (int j = 0; j < 4; j++)
                        s[i][j] += a[i].x * bb[j].x + a[i].y * bb[j].y +
                                   a[i].z * bb[j].z + a[i].w * bb[j].w;
            }
            #pragma unroll
            for (int i = 0; i < 4; i++)
                #pragma unroll
                for (int j = 0; j < 4; j++)
                    sS[(ty * 4 + i) * SS_STRIDE + tx * 4 + j] = s[i][j] * scale;
        }
        __syncthreads();

        // Online softmax per row (threads 0..63, one row each)
        if (t < 64) {
            float* row = sS + t * SS_STRIDE;
            const float m_old = sm[t];
            float mt = m_old;
            #pragma unroll 8
            for (int j = 0; j < 64; j++) mt = fmaxf(mt, row[j]);
            const float fac = __expf(m_old - mt);
            float lsum = 0.0f;
            #pragma unroll 8
            for (int j = 0; j < 64; j++) {
                const float p = __expf(row[j] - mt);
                row[j] = p;
                lsum += p;
            }
            sm[t] = mt;
            sl[t] = sl[t] * fac + lsum;
            sfac[t] = fac;
        }
        __syncthreads();

        // Rescale O by per-row factor; load V tile over sKV
        {
            const float f0 = sfac[ty * 4 + 0];
            const float f1 = sfac[ty * 4 + 1];
            const float f2 = sfac[ty * 4 + 2];
            const float f3 = sfac[ty * 4 + 3];
            #pragma unroll
            for (int c = 0; c < 16; c++) {
                O[0][c] *= f0; O[1][c] *= f1; O[2][c] *= f2; O[3][c] *= f3;
            }
        }
        const float* vbase = qkv + ((size_t)b * TLEN + j0) * QKV3 + 2 * FDIM;
        for (int idx = t; idx < 64 * 64; idx += 256) {
            const int r = idx >> 6, c4 = (idx & 63) << 2;
            *(float4*)(sKV + r * SQ_STRIDE + c4) = *(const float4*)(vbase + (size_t)r * QKV3 + c4);
        }
        __syncthreads();

        // O(4x16) += P(4x64) @ V(64x16 slice)
        #pragma unroll 4
        for (int j = 0; j < 64; j++) {
            const float p0 = sS[(ty * 4 + 0) * SS_STRIDE + j];
            const float p1 = sS[(ty * 4 + 1) * SS_STRIDE + j];
            const float p2 = sS[(ty * 4 + 2) * SS_STRIDE + j];
            const float p3 = sS[(ty * 4 + 3) * SS_STRIDE + j];
            const float* vrow = sKV + j * SQ_STRIDE + tx * 16;
            #pragma unroll
            for (int c = 0; c < 16; c += 4) {
                const float4 v = *(const float4*)(vrow + c);
                O[0][c+0] += p0 * v.x; O[0][c+1] += p0 * v.y; O[0][c+2] += p0 * v.z; O[0][c+3] += p0 * v.w;
                O[1][c+0] += p1 * v.x; O[1][c+1] += p1 * v.y; O[1][c+2] += p1 * v.z; O[1][c+3] += p1 * v.w;
                O[2][c+0] += p2 * v.x; O[2][c+1] += p2 * v.y; O[2][c+2] += p2 * v.z; O[2][c+3] += p2 * v.w;
                O[3][c+0] += p3 * v.x; O[3][c+1] += p3 * v.y; O[3][c+2] += p3 * v.z; O[3][c+3] += p3 * v.w;
            }
        }
    }

    // Normalize and store context (sl final values were visible at last sync)
    const float inv0 = 1.0f / sl[ty * 4 + 0];
    const float inv1 = 1.0f / sl[ty * 4 + 1];
    const float inv2 = 1.0f / sl[ty * 4 + 2];
    const float inv3 = 1.0f / sl[ty * 4 + 3];
    float invs[4] = {inv0, inv1, inv2, inv3};
    #pragma unroll
    for (int i = 0; i < 4; i++) {
        const size_t row = (size_t)b * TLEN + q0 + ty * 4 + i;
        #pragma unroll
        for (int c = 0; c < 16; c += 4) {
            float4 o;
            o.x = O[i][c+0] * invs[i];
            o.y = O[i][c+1] * invs[i];
            o.z = O[i][c+2] * invs[i];
            o.w = O[i][c+3] * invs[i];
            *(float4*)(g_ctx + row * FDIM + tx * 16 + c) = o;
        }
    }
}

// ---------------------------------------------------------------------------
extern "C" void kernel_launch(void* const* d_in, const int* in_sizes, int n_in,
                              void* d_out, int out_size)
{
    const float* inputs = (const float*)d_in[0];
    const float* W_qkv  = (const float*)d_in[1];
    const float* b_qkv  = (const float*)d_in[2];
    const float* W_out  = (const float*)d_in[3];
    const float* b_out  = (const float*)d_in[4];
    float* out = (float*)d_out;

    float* qkv = nullptr;
    float* ctx = nullptr;
    cudaGetSymbolAddress((void**)&qkv, g_qkv);
    cudaGetSymbolAddress((void**)&ctx, g_ctx);

    // 1) QKV projection: [32768,512] @ [512,768] + b
    {
        dim3 grid(QKV3 / 64, MTOT / 64);
        gemm_bias_kernel<<<grid, 256>>>(inputs, W_qkv, b_qkv, qkv, nullptr,
                                        MTOT, QKV3, DIM);
    }

    // 2) Flash attention
    {
        const size_t smem_bytes =
            (2 * 64 * SQ_STRIDE + 64 * SS_STRIDE + 3 * 64) * sizeof(float);
        cudaFuncSetAttribute(flash_attn_kernel,
                             cudaFuncAttributeMaxDynamicSharedMemorySize,
                             (int)smem_bytes);
        dim3 grid(TLEN / 64, BATCH);
        flash_attn_kernel<<<grid, 256, smem_bytes>>>(qkv, ctx);
    }

    // 3) Output projection + residual: inputs + [32768,256] @ [256,512] + b
    {
        dim3 grid(DIM / 64, MTOT / 64);
        gemm_bias_kernel<<<grid, 256>>>(ctx, W_out, b_out, out, inputs,
                                        MTOT, DIM, FDIM);
    }
}

// round 3
// speedup vs baseline: 7.4823x; 7.4823x over previous
#include <cuda_runtime.h>
#include <cstdint>

#define BATCH 16
#define TLEN  2048
#define DIM   512
#define FDIM  256
#define QKV3  768
#define MTOT  (BATCH * TLEN)   // 32768

// ------------------------- scratch (__device__ globals) ---------------------
__device__ float g_x[(size_t)MTOT * DIM];             // rounded inputs
__device__ float g_wq[QKV3 * DIM];                    // rounded W_qkv [512,768]
__device__ float g_wo[DIM * FDIM];                    // rounded W_out [256,512]
__device__ float g_qkv[(size_t)MTOT * QKV3];          // [M,768] q|k|v (rounded)
__device__ float g_s[(size_t)BATCH * TLEN * TLEN];    // [B,T,T] scores/probs
__device__ float g_ctx[(size_t)MTOT * FDIM];          // [M,256] (rounded)

// ------------------------------ helpers -------------------------------------
__device__ __forceinline__ uint32_t smem_u32(const void* p) {
    uint32_t a;
    asm("{ .reg .u64 t; cvta.to.shared.u64 t, %1; cvt.u32.u64 %0, t; }" : "=r"(a) : "l"(p));
    return a;
}
__device__ __forceinline__ float rna_tf32(float x) {
    uint32_t y;
    asm("cvt.rna.tf32.f32 %0, %1;" : "=r"(y) : "f"(x));
    return __uint_as_float(y);
}
#define CP_ASYNC16(dst, src) \
    asm volatile("cp.async.cg.shared.global [%0], [%1], 16;" :: "r"(dst), "l"(src))
#define CP_COMMIT() asm volatile("cp.async.commit_group;" ::: "memory")

__device__ __forceinline__ void mma8(float* c, const uint32_t* a, const uint32_t* b) {
    asm volatile(
        "mma.sync.aligned.m16n8k8.row.col.f32.tf32.tf32.f32 "
        "{%0,%1,%2,%3}, {%4,%5,%6,%7}, {%8,%9}, {%0,%1,%2,%3};"
        : "+f"(c[0]), "+f"(c[1]), "+f"(c[2]), "+f"(c[3])
        : "r"(a[0]), "r"(a[1]), "r"(a[2]), "r"(a[3]), "r"(b[0]), "r"(b[1]));
}

// ------------------------------ tf32 GEMM -----------------------------------
// C[M,N] = scale*(A[M,K] @ opB) + bias + residual (per batch z)
//   BNT=true : B is [N,K] row-major (opB = B^T)
//   BNT=false: B is [K,N] row-major (opB = B)
// Block tile 128x128x32, 8 warps (2x4), warp tile 64x32. cp.async dbl-buffer.
#define ABUF 18432   // 128*36*4
#define SMEM_GEMM (4 * ABUF)

template<bool BNT>
__global__ void __launch_bounds__(256, 2) mma_gemm_kernel(
    const float* __restrict__ A, int lda, long long sA,
    const float* __restrict__ B, int ldb, long long sB,
    float* __restrict__ C, int ldc, long long sC,
    const float* __restrict__ bias, const float* __restrict__ residual,
    float scale, int K, int round_out)
{
    extern __shared__ char smem[];
    const uint32_t sb = smem_u32(smem);
    const int tid  = threadIdx.x;
    const int lane = tid & 31;
    const int wid  = tid >> 5;
    const int wm   = (wid & 1) * 64;   // warp M offset in tile
    const int wn   = (wid >> 1) * 32;  // warp N offset in tile

    const float* Ag = A + blockIdx.z * sA + (size_t)blockIdx.y * 128 * lda;
    const float* Bg;
    if (BNT) Bg = B + blockIdx.z * sB + (size_t)blockIdx.x * 128 * ldb;
    else     Bg = B + blockIdx.z * sB + (size_t)blockIdx.x * 128;

    const int NC = K >> 5;

    // ---- loaders ----
    auto loadA = [&](int c, int s) {
        const int k0 = c << 5;
        const uint32_t base = sb + s * ABUF;
        #pragma unroll
        for (int i = 0; i < 4; i++) {
            const int idx = tid + i * 256;
            const int m = idx >> 3, kq = idx & 7;
            CP_ASYNC16(base + (uint32_t)(m * 36 + kq * 4) * 4,
                       Ag + (size_t)m * lda + k0 + kq * 4);
        }
    };
    auto loadB = [&](int c, int s) {
        const int k0 = c << 5;
        const uint32_t base = sb + 2 * ABUF + s * ABUF;
        if (BNT) {
            #pragma unroll
            for (int i = 0; i < 4; i++) {
                const int idx = tid + i * 256;
                const int n = idx >> 3, kq = idx & 7;
                CP_ASYNC16(base + (uint32_t)(n * 36 + kq * 4) * 4,
                           Bg + (size_t)n * ldb + k0 + kq * 4);
            }
        } else {
            #pragma unroll
            for (int i = 0; i < 4; i++) {
                const int idx = tid + i * 256;
                const int n4 = idx & 31, k = idx >> 5;
                CP_ASYNC16(base + (uint32_t)(k * 136 + n4 * 4) * 4,
                           Bg + (size_t)(k0 + k) * ldb + n4 * 4);
            }
        }
    };

    float acc[4][4][4];
    #pragma unroll
    for (int i = 0; i < 4; i++)
        #pragma unroll
        for (int j = 0; j < 4; j++)
            #pragma unroll
            for (int r = 0; r < 4; r++) acc[i][j][r] = 0.0f;

    loadA(0, 0); loadB(0, 0); CP_COMMIT();

    const int fr = lane >> 2;   // fragment row id 0..7
    const int fc = lane & 3;    // fragment col id 0..3

    for (int c = 0; c < NC; c++) {
        const int s = c & 1;
        if (c + 1 < NC) {
            loadA(c + 1, s ^ 1); loadB(c + 1, s ^ 1); CP_COMMIT();
            asm volatile("cp.async.wait_group 1;" ::: "memory");
        } else {
            asm volatile("cp.async.wait_group 0;" ::: "memory");
        }
        __syncthreads();

        const float* As = (const float*)(smem + s * ABUF);
        const float* Bs = (const float*)(smem + 2 * ABUF + s * ABUF);

        #pragma unroll
        for (int kk = 0; kk < 4; kk++) {
            uint32_t a[4][4], b[4][2];
            #pragma unroll
            for (int mt = 0; mt < 4; mt++) {
                const int row = wm + mt * 16 + fr;
                const int col = kk * 8 + fc;
                a[mt][0] = __float_as_uint(As[row * 36 + col]);
                a[mt][1] = __float_as_uint(As[(row + 8) * 36 + col]);
                a[mt][2] = __float_as_uint(As[row * 36 + col + 4]);
                a[mt][3] = __float_as_uint(As[(row + 8) * 36 + col + 4]);
            }
            #pragma unroll
            for (int nt = 0; nt < 4; nt++) {
                const int n = wn + nt * 8 + fr;
                if (BNT) {
                    b[nt][0] = __float_as_uint(Bs[n * 36 + kk * 8 + fc]);
                    b[nt][1] = __float_as_uint(Bs[n * 36 + kk * 8 + fc + 4]);
                } else {
                    b[nt][0] = __float_as_uint(Bs[(kk * 8 + fc) * 136 + n]);
                    b[nt][1] = __float_as_uint(Bs[(kk * 8 + fc + 4) * 136 + n]);
                }
            }
            #pragma unroll
            for (int mt = 0; mt < 4; mt++)
                #pragma unroll
                for (int nt = 0; nt < 4; nt++)
                    mma8(acc[mt][nt], a[mt], b[nt]);
        }
        __syncthreads();
    }

    // ---- epilogue ----
    const int gm = blockIdx.y * 128 + wm;
    const int gn = blockIdx.x * 128 + wn;
    float* Cb = C + blockIdx.z * sC;

    #pragma unroll
    for (int mt = 0; mt < 4; mt++) {
        #pragma unroll
        for (int nt = 0; nt < 4; nt++) {
            const int col = gn + nt * 8 + fc * 2;
            float2 bb = make_float2(0.f, 0.f);
            if (bias) bb = *(const float2*)(bias + col);
            #pragma unroll
            for (int h = 0; h < 2; h++) {
                const int row = gm + mt * 16 + fr + h * 8;
                float v0 = acc[mt][nt][2 * h + 0] * scale + bb.x;
                float v1 = acc[mt][nt][2 * h + 1] * scale + bb.y;
                if (residual) {
                    const float2 rr = *(const float2*)(residual + (size_t)row * ldc + col);
                    v0 += rr.x; v1 += rr.y;
                }
                if (round_out) { v0 = rna_tf32(v0); v1 = rna_tf32(v1); }
                *(float2*)(Cb + (size_t)row * ldc + col) = make_float2(v0, v1);
            }
        }
    }
}

// ------------------------------ round copy ----------------------------------
__global__ void __launch_bounds__(256) round_kernel(
    const float4* __restrict__ in, float4* __restrict__ out, int n4)
{
    const int i = blockIdx.x * 256 + threadIdx.x;
    if (i < n4) {
        float4 v = in[i];
        v.x = rna_tf32(v.x); v.y = rna_tf32(v.y);
        v.z = rna_tf32(v.z); v.w = rna_tf32(v.w);
        out[i] = v;
    }
}

// ------------------------------- softmax ------------------------------------
__global__ void __launch_bounds__(256) softmax_kernel(float* __restrict__ S)
{
    __shared__ float red[8];
    const size_t row = blockIdx.x;
    float4* p = (float4*)(S + row * TLEN);
    const int t = threadIdx.x;
    float4 a = p[t], b = p[t + 256];

    float m = fmaxf(fmaxf(fmaxf(a.x, a.y), fmaxf(a.z, a.w)),
                    fmaxf(fmaxf(b.x, b.y), fmaxf(b.z, b.w)));
    #pragma unroll
    for (int o = 16; o; o >>= 1) m = fmaxf(m, __shfl_xor_sync(~0u, m, o));
    if ((t & 31) == 0) red[t >> 5] = m;
    __syncthreads();
    m = red[0];
    #pragma unroll
    for (int i = 1; i < 8; i++) m = fmaxf(m, red[i]);
    __syncthreads();

    a.x = __expf(a.x - m); a.y = __expf(a.y - m);
    a.z = __expf(a.z - m); a.w = __expf(a.w - m);
    b.x = __expf(b.x - m); b.y = __expf(b.y - m);
    b.z = __expf(b.z - m); b.w = __expf(b.w - m);

    float ss = a.x + a.y + a.z + a.w + b.x + b.y + b.z + b.w;
    #pragma unroll
    for (int o = 16; o; o >>= 1) ss += __shfl_xor_sync(~0u, ss, o);
    if ((t & 31) == 0) red[t >> 5] = ss;
    __syncthreads();
    ss = red[0];
    #pragma unroll
    for (int i = 1; i < 8; i++) ss += red[i];
    const float inv = 1.0f / ss;

    a.x = rna_tf32(a.x * inv); a.y = rna_tf32(a.y * inv);
    a.z = rna_tf32(a.z * inv); a.w = rna_tf32(a.w * inv);
    b.x = rna_tf32(b.x * inv); b.y = rna_tf32(b.y * inv);
    b.z = rna_tf32(b.z * inv); b.w = rna_tf32(b.w * inv);
    p[t] = a; p[t + 256] = b;
}

// -------------------------------- launch ------------------------------------
extern "C" void kernel_launch(void* const* d_in, const int* in_sizes, int n_in,
                              void* d_out, int out_size)
{
    const float* inputs = (const float*)d_in[0];
    const float* W_qkv  = (const float*)d_in[1];
    const float* b_qkv  = (const float*)d_in[2];
    const float* W_out  = (const float*)d_in[3];
    const float* b_out  = (const float*)d_in[4];
    float* out = (float*)d_out;

    float *x, *wq, *wo, *qkv, *s, *ctx;
    cudaGetSymbolAddress((void**)&x,   g_x);
    cudaGetSymbolAddress((void**)&wq,  g_wq);
    cudaGetSymbolAddress((void**)&wo,  g_wo);
    cudaGetSymbolAddress((void**)&qkv, g_qkv);
    cudaGetSymbolAddress((void**)&s,   g_s);
    cudaGetSymbolAddress((void**)&ctx, g_ctx);

    cudaFuncSetAttribute(mma_gemm_kernel<true>,
                         cudaFuncAttributeMaxDynamicSharedMemorySize, SMEM_GEMM);
    cudaFuncSetAttribute(mma_gemm_kernel<false>,
                         cudaFuncAttributeMaxDynamicSharedMemorySize, SMEM_GEMM);

    // 0) round operands to tf32 (RNA)
    {
        const int nx = MTOT * DIM / 4;
        round_kernel<<<(nx + 255) / 256, 256>>>((const float4*)inputs, (float4*)x, nx);
        const int nq = QKV3 * DIM / 4;
        round_kernel<<<(nq + 255) / 256, 256>>>((const float4*)W_qkv, (float4*)wq, nq);
        const int no = DIM * FDIM / 4;
        round_kernel<<<(no + 255) / 256, 256>>>((const float4*)W_out, (float4*)wo, no);
    }

    // 1) QKV = round(x @ W_qkv + b_qkv)   [32768,512]@[512,768]  (B: NN)
    mma_gemm_kernel<false><<<dim3(QKV3 / 128, MTOT / 128, 1), 256, SMEM_GEMM>>>(
        x, DIM, 0, wq, QKV3, 0, qkv, QKV3, 0, b_qkv, nullptr, 1.0f, DIM, 1);

    // 2) S = (Q @ K^T) / 16   per batch [2048,256]@[256,2048]  (B=K: NT)
    mma_gemm_kernel<true><<<dim3(TLEN / 128, TLEN / 128, BATCH), 256, SMEM_GEMM>>>(
        qkv, QKV3, (long long)TLEN * QKV3,
        qkv + FDIM, QKV3, (long long)TLEN * QKV3,
        s, TLEN, (long long)TLEN * TLEN,
        nullptr, nullptr, 0.0625f, FDIM, 0);

    // 3) row softmax (rounds P to tf32)
    softmax_kernel<<<MTOT, 256>>>(s);

    // 4) ctx = round(P @ V)   per batch [2048,2048]@[2048,256]  (B=V: NN)
    mma_gemm_kernel<false><<<dim3(FDIM / 128, TLEN / 128, BATCH), 256, SMEM_GEMM>>>(
        s, TLEN, (long long)TLEN * TLEN,
        qkv + 2 * FDIM, QKV3, (long long)TLEN * QKV3,
        ctx, FDIM, (long long)TLEN * FDIM,
        nullptr, nullptr, 1.0f, TLEN, 1);

    // 5) out = inputs + ctx @ W_out + b_out   [32768,256]@[256,512]  (B: NN)
    mma_gemm_kernel<false><<<dim3(DIM / 128, MTOT / 128, 1), 256, SMEM_GEMM>>>(
        ctx, FDIM, 0, wo, DIM, 0, out, DIM, 0, b_out, inputs, 1.0f, FDIM, 0);
}

// round 4
// speedup vs baseline: 13.1409x; 1.7563x over previous
#include <cuda_runtime.h>
#include <cuda_bf16.h>
#include <cstdint>

#define BATCH 16
#define TLEN  2048
#define DIM   512
#define FDIM  256
#define QKV3  768
#define MTOT  (BATCH * TLEN)   // 32768

typedef __nv_bfloat16  bf16;
typedef __nv_bfloat162 bf162;

// ------------------------- scratch (__device__ globals) ---------------------
__device__ bf16  g_xb[(size_t)MTOT * DIM];            // inputs bf16
__device__ bf16  g_wqT[QKV3 * DIM];                   // W_qkv^T bf16 [768,512]
__device__ bf16  g_woT[DIM * FDIM];                   // W_out^T bf16 [512,256]
__device__ bf16  g_qkvb[(size_t)MTOT * QKV3];         // [M,768] q|k|v bf16
__device__ float g_s[(size_t)BATCH * TLEN * TLEN];    // scores fp32
__device__ bf16  g_p[(size_t)BATCH * TLEN * TLEN];    // probs bf16
__device__ bf16  g_vT[(size_t)BATCH * FDIM * TLEN];   // [B,256,2048] bf16
__device__ bf16  g_ctxb[(size_t)MTOT * FDIM];         // [M,256] bf16

// ------------------------------ helpers -------------------------------------
__device__ __forceinline__ uint32_t smem_u32(const void* p) {
    uint32_t a;
    asm("{ .reg .u64 t; cvta.to.shared.u64 t, %1; cvt.u32.u64 %0, t; }" : "=r"(a) : "l"(p));
    return a;
}
#define CP_ASYNC16(dst, src) \
    asm volatile("cp.async.cg.shared.global [%0], [%1], 16;" :: "r"(dst), "l"(src))
#define CP_COMMIT() asm volatile("cp.async.commit_group;" ::: "memory")
#define LDSM_X4(r0, r1, r2, r3, addr) \
    asm volatile("ldmatrix.sync.aligned.m8n8.x4.shared.b16 {%0,%1,%2,%3}, [%4];" \
        : "=r"(r0), "=r"(r1), "=r"(r2), "=r"(r3) : "r"(addr))

__device__ __forceinline__ void mma16(float* c, const uint32_t* a, const uint32_t* b) {
    asm volatile(
        "mma.sync.aligned.m16n8k16.row.col.f32.bf16.bf16.f32 "
        "{%0,%1,%2,%3}, {%4,%5,%6,%7}, {%8,%9}, {%0,%1,%2,%3};"
        : "+f"(c[0]), "+f"(c[1]), "+f"(c[2]), "+f"(c[3])
        : "r"(a[0]), "r"(a[1]), "r"(a[2]), "r"(a[3]), "r"(b[0]), "r"(b[1]));
}

// ------------------------------ bf16 NT GEMM --------------------------------
// C[M,N] = scale*(A[M,K] @ B[N,K]^T) + bias (+ residual), per batch z.
// A,B bf16 K-major. Block tile 128x128x64, 8 warps (2x4), warp 64x32.
// smem row stride 72 bf16 (144B) -> ldmatrix conflict-free.
#define SROW   72
#define ATILE  (128 * SROW * 2)        // 18432 B
#define STAGE  (2 * ATILE)             // A+B per stage
#define SMEM_GEMM (2 * STAGE)          // 73728 B

template<bool OUT_BF16>
__global__ void __launch_bounds__(256, 2) bf16_gemm_kernel(
    const bf16* __restrict__ A, int lda, long long sA,
    const bf16* __restrict__ B, int ldb, long long sB,
    void* __restrict__ Cv, int ldc, long long sC,
    const float* __restrict__ bias, const float* __restrict__ residual,
    float scale, int K)
{
    extern __shared__ char smem[];
    const uint32_t sb = smem_u32(smem);
    const int tid  = threadIdx.x;
    const int lane = tid & 31;
    const int wid  = tid >> 5;
    const int wm   = (wid & 1) * 64;
    const int wn   = (wid >> 1) * 32;

    const bf16* Ag = A + blockIdx.z * sA + (size_t)blockIdx.y * 128 * lda;
    const bf16* Bg = B + blockIdx.z * sB + (size_t)blockIdx.x * 128 * ldb;

    const int NC = K >> 6;   // 64-k chunks

    auto loadAB = [&](int c, int s) {
        const int k0 = c << 6;
        const uint32_t ab = sb + s * STAGE;
        const uint32_t bb = ab + ATILE;
        #pragma unroll
        for (int i = 0; i < 4; i++) {
            const int idx = tid + i * 256;
            const int r = idx >> 3, kq = idx & 7;
            CP_ASYNC16(ab + (uint32_t)(r * SROW + kq * 8) * 2,
                       Ag + (size_t)r * lda + k0 + kq * 8);
        }
        #pragma unroll
        for (int i = 0; i < 4; i++) {
            const int idx = tid + i * 256;
            const int r = idx >> 3, kq = idx & 7;
            CP_ASYNC16(bb + (uint32_t)(r * SROW + kq * 8) * 2,
                       Bg + (size_t)r * ldb + k0 + kq * 8);
        }
    };

    float acc[4][4][4];
    #pragma unroll
    for (int i = 0; i < 4; i++)
        #pragma unroll
        for (int j = 0; j < 4; j++)
            #pragma unroll
            for (int r = 0; r < 4; r++) acc[i][j][r] = 0.0f;

    loadAB(0, 0); CP_COMMIT();

    // per-lane ldmatrix base addresses (bytes)
    const uint32_t a_off =
        (uint32_t)((wm + (lane & 15)) * SROW + (lane >> 4) * 8) * 2;
    const uint32_t b_off =
        (uint32_t)((wn + (lane & 7) + ((lane >> 4) & 1) * 8) * SROW +
                   ((lane >> 3) & 1) * 8) * 2;

    for (int c = 0; c < NC; c++) {
        const int s = c & 1;
        if (c + 1 < NC) {
            loadAB(c + 1, s ^ 1); CP_COMMIT();
            asm volatile("cp.async.wait_group 1;" ::: "memory");
        } else {
            asm volatile("cp.async.wait_group 0;" ::: "memory");
        }
        __syncthreads();

        const uint32_t abase = sb + s * STAGE + a_off;
        const uint32_t bbase = sb + s * STAGE + ATILE + b_off;

        #pragma unroll
        for (int kk = 0; kk < 4; kk++) {
            uint32_t a[4][4], b[2][4];
            #pragma unroll
            for (int mt = 0; mt < 4; mt++)
                LDSM_X4(a[mt][0], a[mt][1], a[mt][2], a[mt][3],
                        abase + mt * (16 * SROW * 2) + kk * 32);
            #pragma unroll
            for (int p = 0; p < 2; p++)
                LDSM_X4(b[p][0], b[p][1], b[p][2], b[p][3],
                        bbase + p * (16 * SROW * 2) + kk * 32);
            #pragma unroll
            for (int mt = 0; mt < 4; mt++)
                #pragma unroll
                for (int nt = 0; nt < 4; nt++)
                    mma16(acc[mt][nt], a[mt], &b[nt >> 1][(nt & 1) * 2]);
        }
        __syncthreads();
    }

    // ---- epilogue ----
    const int fr = lane >> 2;
    const int fc = lane & 3;
    const int gm = blockIdx.y * 128 + wm;
    const int gn = blockIdx.x * 128 + wn;

    #pragma unroll
    for (int mt = 0; mt < 4; mt++) {
        #pragma unroll
        for (int nt = 0; nt < 4; nt++) {
            const int col = gn + nt * 8 + fc * 2;
            float2 bb = make_float2(0.f, 0.f);
            if (bias) bb = *(const float2*)(bias + col);
            #pragma unroll
            for (int h = 0; h < 2; h++) {
                const int row = gm + mt * 16 + fr + h * 8;
                float v0 = acc[mt][nt][2 * h + 0] * scale + bb.x;
                float v1 = acc[mt][nt][2 * h + 1] * scale + bb.y;
                if (OUT_BF16) {
                    bf16* Cb = (bf16*)Cv + blockIdx.z * sC;
                    *(bf162*)(Cb + (size_t)row * ldc + col) =
                        __float22bfloat162_rn(make_float2(v0, v1));
                } else {
                    float* Cb = (float*)Cv + blockIdx.z * sC;
                    if (residual) {
                        const float2 rr = *(const float2*)(residual + (size_t)row * ldc + col);
                        v0 += rr.x; v1 += rr.y;
                    }
                    *(float2*)(Cb + (size_t)row * ldc + col) = make_float2(v0, v1);
                }
            }
        }
    }
}

// --------------------------- pack / transpose --------------------------------
__global__ void __launch_bounds__(256) pack_bf16_kernel(
    const float4* __restrict__ in, bf162* __restrict__ out, int n4)
{
    const int i = blockIdx.x * 256 + threadIdx.x;
    if (i < n4) {
        const float4 v = in[i];
        out[2 * i + 0] = __float22bfloat162_rn(make_float2(v.x, v.y));
        out[2 * i + 1] = __float22bfloat162_rn(make_float2(v.z, v.w));
    }
}

// out[c][r] = bf16(in[r][c]);  in: f32 [R,C]
__global__ void __launch_bounds__(256) transpose_pack_kernel(
    const float* __restrict__ in, bf16* __restrict__ out, int ldin, int ldout)
{
    __shared__ float tile[32][33];
    const int tx = threadIdx.x, ty = threadIdx.y;
    const int c0 = blockIdx.x * 32, r0 = blockIdx.y * 32;
    #pragma unroll
    for (int j = 0; j < 32; j += 8)
        tile[ty + j][tx] = in[(size_t)(r0 + ty + j) * ldin + c0 + tx];
    __syncthreads();
    #pragma unroll
    for (int j = 0; j < 32; j += 8)
        out[(size_t)(c0 + ty + j) * ldout + r0 + tx] = __float2bfloat16(tile[tx][ty + j]);
}

// bf16 transpose (for V): out[c][r] = in[r][c]
__global__ void __launch_bounds__(256) transpose_bf16_kernel(
    const bf16* __restrict__ in, bf16* __restrict__ out,
    int ldin, int ldout, long long sin, long long sout)
{
    __shared__ bf16 tile[32][33];
    const bf16* ib = in + blockIdx.z * sin;
    bf16* ob = out + blockIdx.z * sout;
    const int tx = threadIdx.x, ty = threadIdx.y;
    const int c0 = blockIdx.x * 32, r0 = blockIdx.y * 32;
    #pragma unroll
    for (int j = 0; j < 32; j += 8)
        tile[ty + j][tx] = ib[(size_t)(r0 + ty + j) * ldin + c0 + tx];
    __syncthreads();
    #pragma unroll
    for (int j = 0; j < 32; j += 8)
        ob[(size_t)(c0 + ty + j) * ldout + r0 + tx] = tile[tx][ty + j];
}

// ------------------------------- softmax ------------------------------------
// fp32 scores in, bf16 probs out.
__global__ void __launch_bounds__(256) softmax_kernel(
    const float* __restrict__ S, bf16* __restrict__ P)
{
    __shared__ float red[8];
    const size_t row = blockIdx.x;
    const float4* p = (const float4*)(S + row * TLEN);
    bf162* po = (bf162*)(P + row * TLEN);
    const int t = threadIdx.x;
    float4 a = p[t], b = p[t + 256];

    float m = fmaxf(fmaxf(fmaxf(a.x, a.y), fmaxf(a.z, a.w)),
                    fmaxf(fmaxf(b.x, b.y), fmaxf(b.z, b.w)));
    #pragma unroll
    for (int o = 16; o; o >>= 1) m = fmaxf(m, __shfl_xor_sync(~0u, m, o));
    if ((t & 31) == 0) red[t >> 5] = m;
    __syncthreads();
    m = red[0];
    #pragma unroll
    for (int i = 1; i < 8; i++) m = fmaxf(m, red[i]);
    __syncthreads();

    a.x = __expf(a.x - m); a.y = __expf(a.y - m);
    a.z = __expf(a.z - m); a.w = __expf(a.w - m);
    b.x = __expf(b.x - m); b.y = __expf(b.y - m);
    b.z = __expf(b.z - m); b.w = __expf(b.w - m);

    float ss = a.x + a.y + a.z + a.w + b.x + b.y + b.z + b.w;
    #pragma unroll
    for (int o = 16; o; o >>= 1) ss += __shfl_xor_sync(~0u, ss, o);
    if ((t & 31) == 0) red[t >> 5] = ss;
    __syncthreads();
    ss = red[0];
    #pragma unroll
    for (int i = 1; i < 8; i++) ss += red[i];
    const float inv = 1.0f / ss;

    po[2 * t + 0]       = __float22bfloat162_rn(make_float2(a.x * inv, a.y * inv));
    po[2 * t + 1]       = __float22bfloat162_rn(make_float2(a.z * inv, a.w * inv));
    po[512 + 2 * t + 0] = __float22bfloat162_rn(make_float2(b.x * inv, b.y * inv));
    po[512 + 2 * t + 1] = __float22bfloat162_rn(make_float2(b.z * inv, b.w * inv));
}

// -------------------------------- launch ------------------------------------
extern "C" void kernel_launch(void* const* d_in, const int* in_sizes, int n_in,
                              void* d_out, int out_size)
{
    const float* inputs = (const float*)d_in[0];
    const float* W_qkv  = (const float*)d_in[1];
    const float* b_qkv  = (const float*)d_in[2];
    const float* W_out  = (const float*)d_in[3];
    const float* b_out  = (const float*)d_in[4];
    float* out = (float*)d_out;

    bf16 *xb, *wqT, *woT, *qkvb, *p, *vT, *ctxb;
    float* s;
    cudaGetSymbolAddress((void**)&xb,   g_xb);
    cudaGetSymbolAddress((void**)&wqT,  g_wqT);
    cudaGetSymbolAddress((void**)&woT,  g_woT);
    cudaGetSymbolAddress((void**)&qkvb, g_qkvb);
    cudaGetSymbolAddress((void**)&s,    g_s);
    cudaGetSymbolAddress((void**)&p,    g_p);
    cudaGetSymbolAddress((void**)&vT,   g_vT);
    cudaGetSymbolAddress((void**)&ctxb, g_ctxb);

    cudaFuncSetAttribute(bf16_gemm_kernel<true>,
                         cudaFuncAttributeMaxDynamicSharedMemorySize, SMEM_GEMM);
    cudaFuncSetAttribute(bf16_gemm_kernel<false>,
                         cudaFuncAttributeMaxDynamicSharedMemorySize, SMEM_GEMM);

    dim3 tb(32, 8);

    // 0) pack inputs + transpose-pack weights to bf16
    {
        const int nx = MTOT * DIM / 4;
        pack_bf16_kernel<<<(nx + 255) / 256, 256>>>((const float4*)inputs, (bf162*)xb, nx);
        transpose_pack_kernel<<<dim3(QKV3 / 32, DIM / 32), tb>>>(W_qkv, wqT, QKV3, DIM);
        transpose_pack_kernel<<<dim3(DIM / 32, FDIM / 32), tb>>>(W_out, woT, DIM, FDIM);
    }

    // 1) QKV = bf16(x @ W_qkv + b_qkv)   [32768,512]@[512,768]
    bf16_gemm_kernel<true><<<dim3(QKV3 / 128, MTOT / 128, 1), 256, SMEM_GEMM>>>(
        xb, DIM, 0, wqT, DIM, 0, qkvb, QKV3, 0, b_qkv, nullptr, 1.0f, DIM);

    // 1b) V^T per batch: [2048,256] -> [256,2048]
    transpose_bf16_kernel<<<dim3(FDIM / 32, TLEN / 32, BATCH), tb>>>(
        qkvb + 2 * FDIM, vT, QKV3, TLEN,
        (long long)TLEN * QKV3, (long long)FDIM * TLEN);

    // 2) S = (Q @ K^T) / 16  (fp32 out)
    bf16_gemm_kernel<false><<<dim3(TLEN / 128, TLEN / 128, BATCH), 256, SMEM_GEMM>>>(
        qkvb, QKV3, (long long)TLEN * QKV3,
        qkvb + FDIM, QKV3, (long long)TLEN * QKV3,
        s, TLEN, (long long)TLEN * TLEN,
        nullptr, nullptr, 0.0625f, FDIM);

    // 3) softmax rows -> bf16 P
    softmax_kernel<<<MTOT, 256>>>(s, p);

    // 4) ctx = bf16(P @ V)   [2048,2048]@[2048,256] per batch (B = V^T)
    bf16_gemm_kernel<true><<<dim3(FDIM / 128, TLEN / 128, BATCH), 256, SMEM_GEMM>>>(
        p, TLEN, (long long)TLEN * TLEN,
        vT, TLEN, (long long)FDIM * TLEN,
        ctxb, FDIM, (long long)TLEN * FDIM,
        nullptr, nullptr, 1.0f, TLEN);

    // 5) out = inputs + ctx @ W_out + b_out  (fp32 out)
    bf16_gemm_kernel<false><<<dim3(DIM / 128, MTOT / 128, 1), 256, SMEM_GEMM>>>(
        ctxb, FDIM, 0, woT, FDIM, 0, out, DIM, 0, b_out, inputs, 1.0f, FDIM);
}

// round 5
// speedup vs baseline: 13.7031x; 1.0428x over previous
#include <cuda_runtime.h>
#include <cuda_bf16.h>
#include <cstdint>

#define BATCH 16
#define TLEN  2048
#define DIM   512
#define FDIM  256
#define QKV3  768
#define MTOT  (BATCH * TLEN)   // 32768

typedef __nv_bfloat16  bf16;
typedef __nv_bfloat162 bf162;

// ------------------------- scratch (__device__ globals) ---------------------
__device__ bf16 g_xb[(size_t)MTOT * DIM];     // inputs bf16
__device__ bf16 g_wqT[QKV3 * DIM];            // W_qkv^T bf16 [768,512]
__device__ bf16 g_woT[DIM * FDIM];            // W_out^T bf16 [512,256]
__device__ bf16 g_qkvb[(size_t)MTOT * QKV3];  // [M,768] q|k|v bf16
__device__ bf16 g_ctxb[(size_t)MTOT * FDIM];  // [M,256] bf16

// ------------------------------ helpers -------------------------------------
__device__ __forceinline__ uint32_t smem_u32(const void* p) {
    uint32_t a;
    asm("{ .reg .u64 t; cvta.to.shared.u64 t, %1; cvt.u32.u64 %0, t; }" : "=r"(a) : "l"(p));
    return a;
}
#define CP_ASYNC16(dst, src) \
    asm volatile("cp.async.cg.shared.global [%0], [%1], 16;" :: "r"(dst), "l"(src))
#define CP_COMMIT() asm volatile("cp.async.commit_group;" ::: "memory")
#define LDSM_X4(r0, r1, r2, r3, addr) \
    asm volatile("ldmatrix.sync.aligned.m8n8.x4.shared.b16 {%0,%1,%2,%3}, [%4];" \
        : "=r"(r0), "=r"(r1), "=r"(r2), "=r"(r3) : "r"(addr))
#define LDSM_X4T(r0, r1, r2, r3, addr) \
    asm volatile("ldmatrix.sync.aligned.m8n8.x4.trans.shared.b16 {%0,%1,%2,%3}, [%4];" \
        : "=r"(r0), "=r"(r1), "=r"(r2), "=r"(r3) : "r"(addr))

__device__ __forceinline__ void mma16(float* c, const uint32_t* a, const uint32_t* b) {
    asm volatile(
        "mma.sync.aligned.m16n8k16.row.col.f32.bf16.bf16.f32 "
        "{%0,%1,%2,%3}, {%4,%5,%6,%7}, {%8,%9}, {%0,%1,%2,%3};"
        : "+f"(c[0]), "+f"(c[1]), "+f"(c[2]), "+f"(c[3])
        : "r"(a[0]), "r"(a[1]), "r"(a[2]), "r"(a[3]), "r"(b[0]), "r"(b[1]));
}

// ------------------------------ bf16 NT GEMM (round-4, proven) --------------
#define SROW   72
#define ATILE  (128 * SROW * 2)
#define STAGE  (2 * ATILE)
#define SMEM_GEMM (2 * STAGE)

template<bool OUT_BF16>
__global__ void __launch_bounds__(256, 2) bf16_gemm_kernel(
    const bf16* __restrict__ A, int lda, long long sA,
    const bf16* __restrict__ B, int ldb, long long sB,
    void* __restrict__ Cv, int ldc, long long sC,
    const float* __restrict__ bias, const float* __restrict__ residual,
    float scale, int K)
{
    extern __shared__ char smem[];
    const uint32_t sb = smem_u32(smem);
    const int tid  = threadIdx.x;
    const int lane = tid & 31;
    const int wid  = tid >> 5;
    const int wm   = (wid & 1) * 64;
    const int wn   = (wid >> 1) * 32;

    const bf16* Ag = A + blockIdx.z * sA + (size_t)blockIdx.y * 128 * lda;
    const bf16* Bg = B + blockIdx.z * sB + (size_t)blockIdx.x * 128 * ldb;

    const int NC = K >> 6;

    auto loadAB = [&](int c, int s) {
        const int k0 = c << 6;
        const uint32_t ab = sb + s * STAGE;
        const uint32_t bb = ab + ATILE;
        #pragma unroll
        for (int i = 0; i < 4; i++) {
            const int idx = tid + i * 256;
            const int r = idx >> 3, kq = idx & 7;
            CP_ASYNC16(ab + (uint32_t)(r * SROW + kq * 8) * 2,
                       Ag + (size_t)r * lda + k0 + kq * 8);
        }
        #pragma unroll
        for (int i = 0; i < 4; i++) {
            const int idx = tid + i * 256;
            const int r = idx >> 3, kq = idx & 7;
            CP_ASYNC16(bb + (uint32_t)(r * SROW + kq * 8) * 2,
                       Bg + (size_t)r * ldb + k0 + kq * 8);
        }
    };

    float acc[4][4][4];
    #pragma unroll
    for (int i = 0; i < 4; i++)
        #pragma unroll
        for (int j = 0; j < 4; j++)
            #pragma unroll
            for (int r = 0; r < 4; r++) acc[i][j][r] = 0.0f;

    loadAB(0, 0); CP_COMMIT();

    const uint32_t a_off =
        (uint32_t)((wm + (lane & 15)) * SROW + (lane >> 4) * 8) * 2;
    const uint32_t b_off =
        (uint32_t)((wn + (lane & 7) + ((lane >> 4) & 1) * 8) * SROW +
                   ((lane >> 3) & 1) * 8) * 2;

    for (int c = 0; c < NC; c++) {
        const int s = c & 1;
        if (c + 1 < NC) {
            loadAB(c + 1, s ^ 1); CP_COMMIT();
            asm volatile("cp.async.wait_group 1;" ::: "memory");
        } else {
            asm volatile("cp.async.wait_group 0;" ::: "memory");
        }
        __syncthreads();

        const uint32_t abase = sb + s * STAGE + a_off;
        const uint32_t bbase = sb + s * STAGE + ATILE + b_off;

        #pragma unroll
        for (int kk = 0; kk < 4; kk++) {
            uint32_t a[4][4], b[2][4];
            #pragma unroll
            for (int mt = 0; mt < 4; mt++)
                LDSM_X4(a[mt][0], a[mt][1], a[mt][2], a[mt][3],
                        abase + mt * (16 * SROW * 2) + kk * 32);
            #pragma unroll
            for (int p = 0; p < 2; p++)
                LDSM_X4(b[p][0], b[p][1], b[p][2], b[p][3],
                        bbase + p * (16 * SROW * 2) + kk * 32);
            #pragma unroll
            for (int mt = 0; mt < 4; mt++)
                #pragma unroll
                for (int nt = 0; nt < 4; nt++)
                    mma16(acc[mt][nt], a[mt], &b[nt >> 1][(nt & 1) * 2]);
        }
        __syncthreads();
    }

    const int fr = lane >> 2;
    const int fc = lane & 3;
    const int gm = blockIdx.y * 128 + wm;
    const int gn = blockIdx.x * 128 + wn;

    #pragma unroll
    for (int mt = 0; mt < 4; mt++) {
        #pragma unroll
        for (int nt = 0; nt < 4; nt++) {
            const int col = gn + nt * 8 + fc * 2;
            float2 bb = make_float2(0.f, 0.f);
            if (bias) bb = *(const float2*)(bias + col);
            #pragma unroll
            for (int h = 0; h < 2; h++) {
                const int row = gm + mt * 16 + fr + h * 8;
                float v0 = acc[mt][nt][2 * h + 0] * scale + bb.x;
                float v1 = acc[mt][nt][2 * h + 1] * scale + bb.y;
                if (OUT_BF16) {
                    bf16* Cb = (bf16*)Cv + blockIdx.z * sC;
                    *(bf162*)(Cb + (size_t)row * ldc + col) =
                        __float22bfloat162_rn(make_float2(v0, v1));
                } else {
                    float* Cb = (float*)Cv + blockIdx.z * sC;
                    if (residual) {
                        const float2 rr = *(const float2*)(residual + (size_t)row * ldc + col);
                        v0 += rr.x; v1 += rr.y;
                    }
                    *(float2*)(Cb + (size_t)row * ldc + col) = make_float2(v0, v1);
                }
            }
        }
    }
}

// ------------------------------ flash attention -------------------------------
// Per CTA: 128 Q rows x 1 batch. 512 threads = 16 warps (4M x 4N).
// BK=64 key tile, K/V double buffered. O accum in regs, softmax fp32.
#define BK    64
#define QROW  264                 // bf16 row stride for 256-wide tiles
#define PROW  72
#define OFF_K   67584             // 128*264*2
#define OFF_V   135168            // OFF_K + 2*64*264*2
#define OFF_P   202752            // OFF_V + 2*64*264*2
#define OFF_M   221184            // OFF_P + 128*72*2
#define OFF_L   221696
#define OFF_MAX 222208
#define OFF_SUM 224256
#define SMEM_FLASH 226304
#define KVT   33792               // 64*264*2

__global__ void __launch_bounds__(512, 1) flash_kernel(
    const bf16* __restrict__ qkv, bf16* __restrict__ ctx)
{
    extern __shared__ char smem[];
    const uint32_t sb = smem_u32(smem);
    bf16*  sP = (bf16*)(smem + OFF_P);
    float* sM = (float*)(smem + OFF_M);
    float* sL = (float*)(smem + OFF_L);
    float* sMax = (float*)(smem + OFF_MAX);
    float* sSum = (float*)(smem + OFF_SUM);

    const int tid  = threadIdx.x;
    const int lane = tid & 31;
    const int wid  = tid >> 5;
    const int wm   = (wid & 3) * 32;   // Q-row group
    const int wn   = wid >> 2;         // 0..3
    const int fr   = lane >> 2;
    const int fc   = lane & 3;

    const int b  = blockIdx.y;
    const int q0 = blockIdx.x * 128;
    const bf16* qbase  = qkv + ((size_t)b * TLEN + q0) * QKV3;
    const bf16* kvbase = qkv + (size_t)b * TLEN * QKV3;

    if (tid < 128) { sM[tid] = -1e30f; sL[tid] = 0.0f; }

    // load Q (128 x 256)
    #pragma unroll
    for (int i = 0; i < 8; i++) {
        const int idx = tid + i * 512;
        const int r = idx >> 5, c = (idx & 31) * 8;
        CP_ASYNC16(sb + (uint32_t)(r * QROW + c) * 2, qbase + (size_t)r * QKV3 + c);
    }
    auto loadKV = [&](int j, int s) {
        const bf16* kb = kvbase + (size_t)(j * BK) * QKV3 + FDIM;
        const bf16* vb = kvbase + (size_t)(j * BK) * QKV3 + 2 * FDIM;
        const uint32_t kd = sb + OFF_K + s * KVT;
        const uint32_t vd = sb + OFF_V + s * KVT;
        #pragma unroll
        for (int i = 0; i < 4; i++) {
            const int idx = tid + i * 512;
            const int r = idx >> 5, c = (idx & 31) * 8;
            CP_ASYNC16(kd + (uint32_t)(r * QROW + c) * 2, kb + (size_t)r * QKV3 + c);
        }
        #pragma unroll
        for (int i = 0; i < 4; i++) {
            const int idx = tid + i * 512;
            const int r = idx >> 5, c = (idx & 31) * 8;
            CP_ASYNC16(vd + (uint32_t)(r * QROW + c) * 2, vb + (size_t)r * QKV3 + c);
        }
    };
    loadKV(0, 0); CP_COMMIT();

    float acc_o[2][8][4];
    #pragma unroll
    for (int i = 0; i < 2; i++)
        #pragma unroll
        for (int j = 0; j < 8; j++)
            #pragma unroll
            for (int r = 0; r < 4; r++) acc_o[i][j][r] = 0.0f;

    const float scale = 0.0625f;
    const uint32_t aq_off = (uint32_t)((wm + (lane & 15)) * QROW + (lane >> 4) * 8) * 2;
    const uint32_t bk_off = (uint32_t)((wn * 16 + (lane & 7) + ((lane >> 4) & 1) * 8) * QROW +
                                       ((lane >> 3) & 1) * 8) * 2;
    const uint32_t ap_off = (uint32_t)((wm + (lane & 15)) * PROW + (lane >> 4) * 8) * 2;

    for (int j = 0; j < TLEN / BK; j++) {
        const int s = j & 1;
        if (j + 1 < TLEN / BK) {
            loadKV(j + 1, s ^ 1); CP_COMMIT();
            asm volatile("cp.async.wait_group 1;" ::: "memory");
        } else {
            asm volatile("cp.async.wait_group 0;" ::: "memory");
        }
        __syncthreads();

        // ---- S = Q @ K^T (warp tile 32x16) ----
        float acc_s[2][2][4];
        #pragma unroll
        for (int i = 0; i < 2; i++)
            #pragma unroll
            for (int n = 0; n < 2; n++)
                #pragma unroll
                for (int r = 0; r < 4; r++) acc_s[i][n][r] = 0.0f;

        const uint32_t kb = sb + OFF_K + s * KVT;
        #pragma unroll
        for (int kf = 0; kf < 16; kf++) {
            uint32_t a0[4], a1[4], bB[4];
            LDSM_X4(a0[0], a0[1], a0[2], a0[3], sb + aq_off + kf * 32);
            LDSM_X4(a1[0], a1[1], a1[2], a1[3], sb + aq_off + 16 * QROW * 2 + kf * 32);
            LDSM_X4(bB[0], bB[1], bB[2], bB[3], kb + bk_off + kf * 32);
            mma16(acc_s[0][0], a0, &bB[0]);
            mma16(acc_s[0][1], a0, &bB[2]);
            mma16(acc_s[1][0], a1, &bB[0]);
            mma16(acc_s[1][1], a1, &bB[2]);
        }

        // ---- warp row-max over this warp's 16 keys ----
        float mloc[2][2];
        #pragma unroll
        for (int mt = 0; mt < 2; mt++)
            #pragma unroll
            for (int h = 0; h < 2; h++) {
                float mx = fmaxf(fmaxf(acc_s[mt][0][2 * h], acc_s[mt][0][2 * h + 1]),
                                 fmaxf(acc_s[mt][1][2 * h], acc_s[mt][1][2 * h + 1])) * scale;
                mx = fmaxf(mx, __shfl_xor_sync(~0u, mx, 1));
                mx = fmaxf(mx, __shfl_xor_sync(~0u, mx, 2));
                mloc[mt][h] = mx;
            }
        if (fc == 0) {
            #pragma unroll
            for (int mt = 0; mt < 2; mt++)
                #pragma unroll
                for (int h = 0; h < 2; h++)
                    sMax[(wm + mt * 16 + h * 8 + fr) * 4 + wn] = mloc[mt][h];
        }
        __syncthreads();

        // ---- global max, fac, P, psum, O rescale ----
        float fac[2][2], mnew[2][2];
        #pragma unroll
        for (int mt = 0; mt < 2; mt++) {
            #pragma unroll
            for (int h = 0; h < 2; h++) {
                const int r = wm + mt * 16 + h * 8 + fr;
                const float mo = sM[r];
                float mn = fmaxf(fmaxf(sMax[r * 4 + 0], sMax[r * 4 + 1]),
                                 fmaxf(sMax[r * 4 + 2], sMax[r * 4 + 3]));
                mn = fmaxf(mo, mn);
                const float f = __expf(mo - mn);
                mnew[mt][h] = mn; fac[mt][h] = f;

                float p0 = __expf(acc_s[mt][0][2 * h + 0] * scale - mn);
                float p1 = __expf(acc_s[mt][0][2 * h + 1] * scale - mn);
                float p2 = __expf(acc_s[mt][1][2 * h + 0] * scale - mn);
                float p3 = __expf(acc_s[mt][1][2 * h + 1] * scale - mn);

                bf16* pr = sP + r * PROW + wn * 16 + fc * 2;
                *(bf162*)(pr)     = __float22bfloat162_rn(make_float2(p0, p1));
                *(bf162*)(pr + 8) = __float22bfloat162_rn(make_float2(p2, p3));

                float ps = p0 + p1 + p2 + p3;
                ps += __shfl_xor_sync(~0u, ps, 1);
                ps += __shfl_xor_sync(~0u, ps, 2);
                if (fc == 0) sSum[r * 4 + wn] = ps;

                #pragma unroll
                for (int nt = 0; nt < 8; nt++) {
                    acc_o[mt][nt][2 * h + 0] *= f;
                    acc_o[mt][nt][2 * h + 1] *= f;
                }
            }
        }
        __syncthreads();

        if (wn == 0 && fc == 0) {
            #pragma unroll
            for (int mt = 0; mt < 2; mt++)
                #pragma unroll
                for (int h = 0; h < 2; h++) {
                    const int r = wm + mt * 16 + h * 8 + fr;
                    sL[r] = sL[r] * fac[mt][h] +
                            (sSum[r * 4] + sSum[r * 4 + 1] + sSum[r * 4 + 2] + sSum[r * 4 + 3]);
                    sM[r] = mnew[mt][h];
                }
        }

        // ---- O += P @ V (warp tile 32x64) ----
        const uint32_t vb = sb + OFF_V + s * KVT;
        const int t2 = lane >> 3;
        #pragma unroll
        for (int kf = 0; kf < 4; kf++) {
            uint32_t a0[4], a1[4];
            LDSM_X4(a0[0], a0[1], a0[2], a0[3], sb + OFF_P + ap_off + kf * 32);
            LDSM_X4(a1[0], a1[1], a1[2], a1[3], sb + OFF_P + ap_off + 16 * PROW * 2 + kf * 32);
            #pragma unroll
            for (int p = 0; p < 4; p++) {
                uint32_t v[4];
                const int krow = kf * 16 + (t2 & 1) * 8 + (lane & 7);
                const int ncol = wn * 64 + p * 16 + (t2 >> 1) * 8;
                LDSM_X4T(v[0], v[1], v[2], v[3],
                         vb + (uint32_t)(krow * QROW + ncol) * 2);
                mma16(acc_o[0][p * 2 + 0], a0, &v[0]);
                mma16(acc_o[0][p * 2 + 1], a0, &v[2]);
                mma16(acc_o[1][p * 2 + 0], a1, &v[0]);
                mma16(acc_o[1][p * 2 + 1], a1, &v[2]);
            }
        }
        __syncthreads();
    }

    // ---- normalize + store ----
    #pragma unroll
    for (int mt = 0; mt < 2; mt++) {
        #pragma unroll
        for (int h = 0; h < 2; h++) {
            const int r = wm + mt * 16 + h * 8 + fr;
            const float inv = 1.0f / sL[r];
            bf16* orow = ctx + ((size_t)b * TLEN + q0 + r) * FDIM;
            #pragma unroll
            for (int nt = 0; nt < 8; nt++) {
                const int col = wn * 64 + nt * 8 + fc * 2;
                *(bf162*)(orow + col) = __float22bfloat162_rn(
                    make_float2(acc_o[mt][nt][2 * h + 0] * inv,
                                acc_o[mt][nt][2 * h + 1] * inv));
            }
        }
    }
}

// --------------------------- pack / transpose --------------------------------
__global__ void __launch_bounds__(256) pack_bf16_kernel(
    const float4* __restrict__ in, bf162* __restrict__ out, int n4)
{
    const int i = blockIdx.x * 256 + threadIdx.x;
    if (i < n4) {
        const float4 v = in[i];
        out[2 * i + 0] = __float22bfloat162_rn(make_float2(v.x, v.y));
        out[2 * i + 1] = __float22bfloat162_rn(make_float2(v.z, v.w));
    }
}

__global__ void __launch_bounds__(256) transpose_pack_kernel(
    const float* __restrict__ in, bf16* __restrict__ out, int ldin, int ldout)
{
    __shared__ float tile[32][33];
    const int tx = threadIdx.x, ty = threadIdx.y;
    const int c0 = blockIdx.x * 32, r0 = blockIdx.y * 32;
    #pragma unroll
    for (int j = 0; j < 32; j += 8)
        tile[ty + j][tx] = in[(size_t)(r0 + ty + j) * ldin + c0 + tx];
    __syncthreads();
    #pragma unroll
    for (int j = 0; j < 32; j += 8)
        out[(size_t)(c0 + ty + j) * ldout + r0 + tx] = __float2bfloat16(tile[tx][ty + j]);
}

// -------------------------------- launch ------------------------------------
extern "C" void kernel_launch(void* const* d_in, const int* in_sizes, int n_in,
                              void* d_out, int out_size)
{
    const float* inputs = (const float*)d_in[0];
    const float* W_qkv  = (const float*)d_in[1];
    const float* b_qkv  = (const float*)d_in[2];
    const float* W_out  = (const float*)d_in[3];
    const float* b_out  = (const float*)d_in[4];
    float* out = (float*)d_out;

    bf16 *xb, *wqT, *woT, *qkvb, *ctxb;
    cudaGetSymbolAddress((void**)&xb,   g_xb);
    cudaGetSymbolAddress((void**)&wqT,  g_wqT);
    cudaGetSymbolAddress((void**)&woT,  g_woT);
    cudaGetSymbolAddress((void**)&qkvb, g_qkvb);
    cudaGetSymbolAddress((void**)&ctxb, g_ctxb);

    cudaFuncSetAttribute(bf16_gemm_kernel<true>,
                         cudaFuncAttributeMaxDynamicSharedMemorySize, SMEM_GEMM);
    cudaFuncSetAttribute(bf16_gemm_kernel<false>,
                         cudaFuncAttributeMaxDynamicSharedMemorySize, SMEM_GEMM);
    cudaFuncSetAttribute(flash_kernel,
                         cudaFuncAttributeMaxDynamicSharedMemorySize, SMEM_FLASH);

    dim3 tb(32, 8);

    // 0) pack inputs + transpose-pack weights to bf16
    {
        const int nx = MTOT * DIM / 4;
        pack_bf16_kernel<<<(nx + 255) / 256, 256>>>((const float4*)inputs, (bf162*)xb, nx);
        transpose_pack_kernel<<<dim3(QKV3 / 32, DIM / 32), tb>>>(W_qkv, wqT, QKV3, DIM);
        transpose_pack_kernel<<<dim3(DIM / 32, FDIM / 32), tb>>>(W_out, woT, DIM, FDIM);
    }

    // 1) QKV = bf16(x @ W_qkv + b_qkv)
    bf16_gemm_kernel<true><<<dim3(QKV3 / 128, MTOT / 128, 1), 256, SMEM_GEMM>>>(
        xb, DIM, 0, wqT, DIM, 0, qkvb, QKV3, 0, b_qkv, nullptr, 1.0f, DIM);

    // 2) fused attention -> ctx (bf16)
    flash_kernel<<<dim3(TLEN / 128, BATCH), 512, SMEM_FLASH>>>(qkvb, ctxb);

    // 3) out = inputs + ctx @ W_out + b_out  (fp32)
    bf16_gemm_kernel<false><<<dim3(DIM / 128, MTOT / 128, 1), 256, SMEM_GEMM>>>(
        ctxb, FDIM, 0, woT, FDIM, 0, out, DIM, 0, b_out, inputs, 1.0f, FDIM);
}